// round 2
// baseline (speedup 1.0000x reference)
#include <cuda_runtime.h>

#define N_NODES 2048
#define D 64
#define TI 16
#define TJ 16

// Precomputed per-node first-layer partials (device scratch; allocation-free).
__device__ float g_A[N_NODES * D];   // X @ W1[0:64]  + b1
__device__ float g_B[N_NODES * D];   // X @ W1[64:128]

// ---------------------------------------------------------------------------
// Packed f32x2 helpers (Blackwell FFMA2 path)
// ---------------------------------------------------------------------------
__device__ __forceinline__ unsigned long long pack2(float lo, float hi) {
    unsigned long long r;
    asm("mov.b64 %0, {%1, %2};" : "=l"(r) : "f"(lo), "f"(hi));
    return r;
}
__device__ __forceinline__ unsigned long long bcast2(float v) {
    unsigned long long r;
    asm("mov.b64 %0, {%1, %1};" : "=l"(r) : "f"(v));
    return r;
}
__device__ __forceinline__ void unpack2(unsigned long long p, float& lo, float& hi) {
    asm("mov.b64 {%0, %1}, %2;" : "=f"(lo), "=f"(hi) : "l"(p));
}
__device__ __forceinline__ unsigned long long fma2(unsigned long long a,
                                                   unsigned long long b,
                                                   unsigned long long c) {
    unsigned long long r;
    asm("fma.rn.f32x2 %0, %1, %2, %3;" : "=l"(r) : "l"(a), "l"(b), "l"(c));
    return r;
}

// ---------------------------------------------------------------------------
// Phase 1: A[n] = x_n @ W1[0:64] + b1 ; B[n] = x_n @ W1[64:128]
// ---------------------------------------------------------------------------
__global__ void precompute_AB(const float* __restrict__ X,
                              const float* __restrict__ W1,
                              const float* __restrict__ b1) {
    __shared__ float xs[D];
    int n = blockIdx.x;
    int d = threadIdx.x;
    xs[d] = X[n * D + d];
    float a = b1[d];
    __syncthreads();
    float b = 0.f;
#pragma unroll 8
    for (int k = 0; k < D; k++) {
        float xv = xs[k];
        a = fmaf(xv, W1[k * D + d], a);
        b = fmaf(xv, W1[(D + k) * D + d], b);
    }
    g_A[n * D + d] = a;
    g_B[n * D + d] = b;
}

// ---------------------------------------------------------------------------
// Phase 2: per pair (i<j):
//   h1 = relu(A[i] + B[j])
//   h2 = relu(h1 @ W2 + b2)
//   out[p, 0:9] = h2 @ [We | Wt] + [be | bt]
// Tiled 16x16 pairs per 256-thread block; FFMA2 packed accumulation.
// ---------------------------------------------------------------------------
__global__ __launch_bounds__(256, 2)
void edge_kernel(const float* __restrict__ W2,
                 const float* __restrict__ b2,
                 const float* __restrict__ We,
                 const float* __restrict__ be,
                 const float* __restrict__ Wt,
                 const float* __restrict__ bt,
                 float* __restrict__ out) {
    __shared__ float As[TI * 65];              // padded: conflict-free
    __shared__ float Bs[TJ * 65];
    __shared__ float4 W2s[D * 16];             // row k = 16 float4 = 64 floats
    __shared__ float b2s[D];
    __shared__ unsigned long long Wop[D * 5];  // fused heads, width 10 floats, packed
    __shared__ float bos[10];

    int bi = blockIdx.y, bj = blockIdx.x;
    if (bj < bi) return;                       // upper-triangle tiles only
    int tid = threadIdx.x;

    for (int idx = tid; idx < TI * D; idx += 256) {
        int r = idx >> 6, c = idx & 63;
        As[r * 65 + c] = g_A[(bi * TI + r) * D + c];
        Bs[r * 65 + c] = g_B[(bj * TJ + r) * D + c];
    }
    for (int idx = tid; idx < D * 16; idx += 256)
        W2s[idx] = ((const float4*)W2)[idx];
    if (tid < D) b2s[tid] = b2[tid];
    {
        float* Wof = (float*)Wop;
        for (int idx = tid; idx < D * 10; idx += 256) {
            int d = idx / 10, e = idx % 10;
            float v = 0.f;
            if (e == 0)      v = We[d];
            else if (e < 9)  v = Wt[d * 8 + (e - 1)];
            Wof[idx] = v;
        }
    }
    if (tid < 10) bos[tid] = (tid == 0) ? be[0] : (tid < 9 ? bt[tid - 1] : 0.f);
    __syncthreads();

    int ti = tid >> 4, tj = tid & 15;
    int i = bi * TI + ti, j = bj * TJ + tj;

    // h2 accumulators: 64 floats as 32 packed f32x2
    unsigned long long acc[32];
#pragma unroll
    for (int d2 = 0; d2 < 32; d2++)
        acc[d2] = pack2(b2s[2 * d2], b2s[2 * d2 + 1]);

    const ulonglong2* W2q = reinterpret_cast<const ulonglong2*>(W2s);
    const float* Ar = &As[ti * 65];
    const float* Br = &Bs[tj * 65];

#pragma unroll 4
    for (int k = 0; k < D; k++) {
        float h1 = fmaxf(Ar[k] + Br[k], 0.f);
        unsigned long long hp = bcast2(h1);
        const ulonglong2* wrow = W2q + k * 16;   // 16 x (2 packed) = 64 floats
#pragma unroll
        for (int q = 0; q < 16; q++) {
            ulonglong2 w = wrow[q];
            acc[2 * q]     = fma2(hp, w.x, acc[2 * q]);
            acc[2 * q + 1] = fma2(hp, w.y, acc[2 * q + 1]);
        }
    }

    // Fused heads: out10 = relu(h2) @ Wop + bos  (slot 9 is padding)
    unsigned long long oacc[5];
#pragma unroll
    for (int e2 = 0; e2 < 5; e2++)
        oacc[e2] = pack2(bos[2 * e2], bos[2 * e2 + 1]);

#pragma unroll 4
    for (int d2 = 0; d2 < 32; d2++) {
        float lo, hi;
        unpack2(acc[d2], lo, hi);
        lo = fmaxf(lo, 0.f);
        hi = fmaxf(hi, 0.f);
        unsigned long long lp = bcast2(lo);
        unsigned long long hp = bcast2(hi);
        const unsigned long long* w0 = &Wop[(2 * d2) * 5];
        const unsigned long long* w1 = &Wop[(2 * d2 + 1) * 5];
#pragma unroll
        for (int e2 = 0; e2 < 5; e2++) {
            oacc[e2] = fma2(lp, w0[e2], oacc[e2]);
            oacc[e2] = fma2(hp, w1[e2], oacc[e2]);
        }
    }

    if (i < j) {
        // row-major upper-triangle linear index
        int p = i * (2 * N_NODES - i - 1) / 2 + (j - i - 1);
        float o[10];
#pragma unroll
        for (int e2 = 0; e2 < 5; e2++) unpack2(oacc[e2], o[2 * e2], o[2 * e2 + 1]);
        float* dst = out + (long long)p * 9;
#pragma unroll
        for (int e = 0; e < 9; e++) dst[e] = o[e];
    }
}

extern "C" void kernel_launch(void* const* d_in, const int* in_sizes, int n_in,
                              void* d_out, int out_size) {
    const float* X  = (const float*)d_in[0];
    const float* W1 = (const float*)d_in[1];
    const float* b1 = (const float*)d_in[2];
    const float* W2 = (const float*)d_in[3];
    const float* b2 = (const float*)d_in[4];
    const float* We = (const float*)d_in[5];
    const float* be = (const float*)d_in[6];
    const float* Wt = (const float*)d_in[7];
    const float* bt = (const float*)d_in[8];
    float* out = (float*)d_out;

    precompute_AB<<<N_NODES, D>>>(X, W1, b1);
    dim3 grid(N_NODES / TJ, N_NODES / TI);
    edge_kernel<<<grid, 256>>>(W2, b2, We, be, Wt, bt, out);
}

// round 5
// speedup vs baseline: 1.5977x; 1.5977x over previous
#include <cuda_runtime.h>

#define N_NODES 2048
#define D 64
#define TP 16    // pair tile per dim -> 16x16 = 256 pairs per block

typedef unsigned long long u64;

// Precomputed per-node first-layer partials (device scratch; allocation-free).
__device__ float g_A[N_NODES * D];   // X @ W1[0:64]  + b1
__device__ float g_B[N_NODES * D];   // X @ W1[64:128]

// ---------------------------------------------------------------------------
// Packed f32x2 helpers (Blackwell FFMA2 path)
// ---------------------------------------------------------------------------
__device__ __forceinline__ u64 pack2(float lo, float hi) {
    u64 r; asm("mov.b64 %0, {%1, %2};" : "=l"(r) : "f"(lo), "f"(hi)); return r;
}
__device__ __forceinline__ u64 bcast2(float v) {
    u64 r; asm("mov.b64 %0, {%1, %1};" : "=l"(r) : "f"(v)); return r;
}
__device__ __forceinline__ void unpack2(u64 p, float& lo, float& hi) {
    asm("mov.b64 {%0, %1}, %2;" : "=f"(lo), "=f"(hi) : "l"(p));
}
__device__ __forceinline__ u64 fma2(u64 a, u64 b, u64 c) {
    u64 r; asm("fma.rn.f32x2 %0, %1, %2, %3;" : "=l"(r) : "l"(a), "l"(b), "l"(c));
    return r;
}

// ---------------------------------------------------------------------------
// Phase 1: A[n] = x_n @ W1[0:64] + b1 ; B[n] = x_n @ W1[64:128]
// ---------------------------------------------------------------------------
__global__ void precompute_AB(const float* __restrict__ X,
                              const float* __restrict__ W1,
                              const float* __restrict__ b1) {
    __shared__ float xs[D];
    int n = blockIdx.x;
    int d = threadIdx.x;
    xs[d] = X[n * D + d];
    float a = b1[d];
    __syncthreads();
    float b = 0.f;
#pragma unroll 8
    for (int k = 0; k < D; k++) {
        float xv = xs[k];
        a = fmaf(xv, W1[k * D + d], a);
        b = fmaf(xv, W1[(D + k) * D + d], b);
    }
    g_A[n * D + d] = a;
    g_B[n * D + d] = b;
}

// ---------------------------------------------------------------------------
// Phase 2. Thread layout: tid = pg*4 + cg
//   cg  (lane bits 0-1): column group, owns output cols [cg*16, cg*16+16)
//   pg  = tid>>2 in [0,64): pair group = 2x2 pairs at (i0,j0) = (2*(pg>>3), 2*(pg&7))
// Each thread: 4 pairs x 16 cols of h2 in 32 packed f32x2 accumulators.
// W2 slice loads amortized over 4 pairs -> no longer LDS-bound.
// Heads: per-thread partials over owned 16 cols, shfl.xor reduce across cg.
// ---------------------------------------------------------------------------
__global__ __launch_bounds__(256, 2)
void edge_kernel(const float* __restrict__ W2,
                 const float* __restrict__ b2,
                 const float* __restrict__ We,
                 const float* __restrict__ be,
                 const float* __restrict__ Wt,
                 const float* __restrict__ bt,
                 float* __restrict__ out) {
    __shared__ __align__(16) float As[D][18];   // [k][i_local], pad 18 (8B-aligned even cols)
    __shared__ __align__(16) float Bs[D][18];   // [k][j_local]
    __shared__ __align__(16) float4 W2s4[D * 16]; // [k][n] row-major, 64 floats/row
    __shared__ u64  b2p[32];                     // b2 packed f32x2
    __shared__ u64  Wop[D * 5];                  // fused heads [d][e2], width 10 floats
    __shared__ float bos[10];

    int bi = blockIdx.y, bj = blockIdx.x;
    if (bj < bi) return;                         // upper-triangle tiles only
    int tid = threadIdx.x;

    // Stage A/B transposed: As[k][i_local]
    for (int idx = tid; idx < TP * D; idx += 256) {
        int r = idx >> 6, c = idx & 63;
        As[c][r] = g_A[(bi * TP + r) * D + c];
        Bs[c][r] = g_B[(bj * TP + r) * D + c];
    }
    for (int idx = tid; idx < D * 16; idx += 256)
        W2s4[idx] = ((const float4*)W2)[idx];
    if (tid < 32) b2p[tid] = pack2(b2[2 * tid], b2[2 * tid + 1]);
    {
        float* Wof = (float*)Wop;
        for (int idx = tid; idx < D * 10; idx += 256) {
            int d = idx / 10, e = idx % 10;
            float v = 0.f;
            if (e == 0)      v = We[d];
            else if (e < 9)  v = Wt[d * 8 + (e - 1)];
            Wof[idx] = v;
        }
    }
    if (tid < 10) bos[tid] = (tid == 0) ? be[0] : (tid < 9 ? bt[tid - 1] : 0.f);
    __syncthreads();

    int cg = tid & 3;
    int pg = tid >> 2;
    int gi = pg >> 3, gj = pg & 7;
    int i0 = gi * 2, j0 = gj * 2;
    int c0 = cg * 16;

    // acc[pair][q]: pair = di*2+dj; q indexes 8 packed f32x2 = 16 cols
    u64 acc[4][8];
#pragma unroll
    for (int q = 0; q < 8; q++) {
        u64 b = b2p[cg * 8 + q];
        acc[0][q] = b; acc[1][q] = b; acc[2][q] = b; acc[3][q] = b;
    }

    const ulonglong2* W2q = reinterpret_cast<const ulonglong2*>(W2s4);

#pragma unroll 4
    for (int k = 0; k < D; k++) {
        float2 av = *(const float2*)&As[k][i0];
        float2 bv = *(const float2*)&Bs[k][j0];
        u64 h0 = bcast2(fmaxf(av.x + bv.x, 0.f));  // pair (0,0)
        u64 h1 = bcast2(fmaxf(av.x + bv.y, 0.f));  // pair (0,1)
        u64 h2 = bcast2(fmaxf(av.y + bv.x, 0.f));  // pair (1,0)
        u64 h3 = bcast2(fmaxf(av.y + bv.y, 0.f));  // pair (1,1)
        const ulonglong2* wr = W2q + k * 16 + cg * 4;
#pragma unroll
        for (int q2 = 0; q2 < 4; q2++) {
            ulonglong2 w = wr[q2];
            acc[0][2*q2]   = fma2(h0, w.x, acc[0][2*q2]);
            acc[0][2*q2+1] = fma2(h0, w.y, acc[0][2*q2+1]);
            acc[1][2*q2]   = fma2(h1, w.x, acc[1][2*q2]);
            acc[1][2*q2+1] = fma2(h1, w.y, acc[1][2*q2+1]);
            acc[2][2*q2]   = fma2(h2, w.x, acc[2][2*q2]);
            acc[2][2*q2+1] = fma2(h2, w.y, acc[2][2*q2+1]);
            acc[3][2*q2]   = fma2(h3, w.x, acc[3][2*q2]);
            acc[3][2*q2+1] = fma2(h3, w.y, acc[3][2*q2+1]);
        }
    }

    // Heads: partial over this thread's 16 cols -> 10 packed outputs per pair.
    u64 oacc[4][5];
#pragma unroll
    for (int p = 0; p < 4; p++)
#pragma unroll
        for (int e2 = 0; e2 < 5; e2++) oacc[p][e2] = 0ull;

#pragma unroll
    for (int q = 0; q < 8; q++) {
        const u64* w0 = &Wop[(c0 + 2 * q) * 5];
        const u64* w1 = w0 + 5;
        u64 w0r[5], w1r[5];
#pragma unroll
        for (int e2 = 0; e2 < 5; e2++) { w0r[e2] = w0[e2]; w1r[e2] = w1[e2]; }
#pragma unroll
        for (int p = 0; p < 4; p++) {
            float lo, hi;
            unpack2(acc[p][q], lo, hi);
            u64 lp = bcast2(fmaxf(lo, 0.f));
            u64 hp = bcast2(fmaxf(hi, 0.f));
#pragma unroll
            for (int e2 = 0; e2 < 5; e2++) {
                oacc[p][e2] = fma2(lp, w0r[e2], oacc[p][e2]);
                oacc[p][e2] = fma2(hp, w1r[e2], oacc[p][e2]);
            }
        }
    }

    // Reduce across the 4 cg lanes (lane bits 0-1) and write pair p == cg.
#pragma unroll
    for (int p = 0; p < 4; p++) {
        float o[10];
#pragma unroll
        for (int e2 = 0; e2 < 5; e2++) unpack2(oacc[p][e2], o[2 * e2], o[2 * e2 + 1]);
#pragma unroll
        for (int e = 0; e < 10; e++) {
            o[e] += __shfl_xor_sync(0xFFFFFFFF, o[e], 1);
            o[e] += __shfl_xor_sync(0xFFFFFFFF, o[e], 2);
        }
        if (cg == p) {
            int i = bi * TP + i0 + (p >> 1);
            int j = bj * TP + j0 + (p & 1);
            if (i < j) {
                int pidx = i * (2 * N_NODES - i - 1) / 2 + (j - i - 1);
                float* dst = out + (long long)pidx * 9;
#pragma unroll
                for (int e = 0; e < 9; e++) dst[e] = o[e] + bos[e];
            }
        }
    }
}

extern "C" void kernel_launch(void* const* d_in, const int* in_sizes, int n_in,
                              void* d_out, int out_size) {
    const float* X  = (const float*)d_in[0];
    const float* W1 = (const float*)d_in[1];
    const float* b1 = (const float*)d_in[2];
    const float* W2 = (const float*)d_in[3];
    const float* b2 = (const float*)d_in[4];
    const float* We = (const float*)d_in[5];
    const float* be = (const float*)d_in[6];
    const float* Wt = (const float*)d_in[7];
    const float* bt = (const float*)d_in[8];
    float* out = (float*)d_out;

    precompute_AB<<<N_NODES, D>>>(X, W1, b1);
    dim3 grid(N_NODES / TP, N_NODES / TP);
    edge_kernel<<<grid, 256>>>(W2, b2, We, be, Wt, bt, out);
}